// round 12
// baseline (speedup 1.0000x reference)
#include <cuda_runtime.h>
#include <cuda_fp16.h>
#include <cstdint>

// ======================= problem dims =======================
static constexpr int T_TOK = 2048;
static constexpr int D_DIM = 2048;
static constexpr int N_OUT = 11264;   // 2*BDIM
static constexpr int BDIM  = 5632;
static constexpr int L_EXP = 16;

// ======================= GEMM tiling ========================
static constexpr int BM = 128;
static constexpr int BN = 128;
static constexpr int BK = 64;                  // fp16 K per stage (128B per row)
static constexpr int K_ITERS = D_DIM / BK;     // 32
static constexpr int MT = T_TOK / BM;          // 16
static constexpr int NT = N_OUT / BN;          // 88
static constexpr int STAGES = 3;

// pitch 144B (9x16B, 9 coprime 8 -> conflict-free ldmatrix, swizzle-free)
static constexpr int PITCH_B = 144;
static constexpr int TILE_B  = BM * PITCH_B;             // 18432
static constexpr int STAGE_B = 2 * TILE_B;               // 36864 (A + B tile)
static constexpr int SMEM_GEMM = STAGES * STAGE_B;       // 110592 -> 2 CTAs/SM

// ================= device scratch (static, legal) =================
__device__ __half g_xh[(size_t)T_TOK * D_DIM];   // x rows PERMUTED into sorted-slot order
__device__ __half g_Wh[(size_t)N_OUT * D_DIM];
__device__ int    g_tok_sorted[T_TOK];           // slot -> token
__device__ int    g_slot_expert[T_TOK];          // slot -> expert
__device__ int    g_expert_start[L_EXP + 1];
__device__ float  g_xa[T_TOK * 32];              // slot-major, 32 ranks (both halves)

// ======================= helpers ========================
__device__ __forceinline__ uint32_t smem_u32(const void* p) {
    uint32_t a;
    asm("{ .reg .u64 t; cvta.to.shared.u64 t, %1; cvt.u32.u64 %0, t; }" : "=r"(a) : "l"(p));
    return a;
}
__device__ __forceinline__ void cp_async16(uint32_t saddr, const void* g) {
    asm volatile("cp.async.cg.shared.global [%0], [%1], 16;" :: "r"(saddr), "l"(g));
}
#define CP_COMMIT()  asm volatile("cp.async.commit_group;" ::: "memory")
#define CP_WAIT(N)   asm volatile("cp.async.wait_group %0;" :: "n"(N) : "memory")

__device__ __forceinline__ void ldsm_x4(uint32_t* r, uint32_t addr) {
    asm volatile("ldmatrix.sync.aligned.m8n8.x4.shared.b16 {%0,%1,%2,%3}, [%4];"
                 : "=r"(r[0]), "=r"(r[1]), "=r"(r[2]), "=r"(r[3]) : "r"(addr));
}
__device__ __forceinline__ void mma_f16(float* d, const uint32_t* a, const uint32_t* b) {
    asm volatile(
        "mma.sync.aligned.m16n8k16.row.col.f32.f16.f16.f32 "
        "{%0,%1,%2,%3}, {%4,%5,%6,%7}, {%8,%9}, {%0,%1,%2,%3};"
        : "+f"(d[0]), "+f"(d[1]), "+f"(d[2]), "+f"(d[3])
        : "r"(a[0]), "r"(a[1]), "r"(a[2]), "r"(a[3]), "r"(b[0]), "r"(b[1]));
}

// ================= W convert =================
__global__ void __launch_bounds__(256) convert_W_kernel(
    const float4* __restrict__ src, uint2* __restrict__ dst, int n4)
{
    const int i0 = (blockIdx.x * 256 + threadIdx.x) * 2;
    #pragma unroll
    for (int j = 0; j < 2; j++) {
        const int i = i0 + j;
        if (i < n4) {
            const float4 v = src[i];
            __half2 h0 = __floats2half2_rn(v.x, v.y);
            __half2 h1 = __floats2half2_rn(v.z, v.w);
            uint2 u;
            u.x = *reinterpret_cast<uint32_t*>(&h0);
            u.y = *reinterpret_cast<uint32_t*>(&h1);
            dst[i] = u;
        }
    }
}

// permuted x convert: slot row <- token row (one block per slot); runs after sort
__global__ void __launch_bounds__(256) convert_x_perm_kernel(
    const float4* __restrict__ x4, uint2* __restrict__ dst)
{
    const int slot = blockIdx.x;
    const int tok  = g_tok_sorted[slot];
    const float4* src = x4 + (size_t)tok * (D_DIM / 4);
    uint2* d = dst + (size_t)slot * (D_DIM / 4);
    #pragma unroll
    for (int j = 0; j < 2; j++) {
        const int i = threadIdx.x + j * 256;
        const float4 v = src[i];
        __half2 h0 = __floats2half2_rn(v.x, v.y);
        __half2 h1 = __floats2half2_rn(v.z, v.w);
        uint2 u;
        u.x = *reinterpret_cast<uint32_t*>(&h0);
        u.y = *reinterpret_cast<uint32_t*>(&h1);
        d[i] = u;
    }
}

// ======================= sort (+ fused g_xa zero) =========================
// weight_indices buffer is int32 (JAX x64-disabled downgrades int64 silently)
__global__ void sort_kernel(const int* __restrict__ widx)
{
    // fused zero of g_xa (64 float4 per thread)
    {
        float4* z = reinterpret_cast<float4*>(g_xa);
        const float4 zero = make_float4(0.f, 0.f, 0.f, 0.f);
        for (int i = threadIdx.x; i < T_TOK * 32 / 4; i += 256) z[i] = zero;
    }
    __shared__ int cnt[L_EXP];
    __shared__ int off[L_EXP];
    __shared__ int starts[L_EXP + 1];
    const int tid = threadIdx.x;
    if (tid < L_EXP) cnt[tid] = 0;
    __syncthreads();
    for (int t = tid; t < T_TOK; t += 256) atomicAdd(&cnt[widx[t] & (L_EXP - 1)], 1);
    __syncthreads();
    if (tid == 0) {
        int s = 0;
        for (int l = 0; l < L_EXP; l++) { starts[l] = s; s += cnt[l]; }
        starts[L_EXP] = s;
    }
    __syncthreads();
    if (tid < L_EXP) off[tid] = starts[tid];
    if (tid < L_EXP + 1) g_expert_start[tid] = starts[tid];
    __syncthreads();
    for (int t = tid; t < T_TOK; t += 256) {
        const int l = widx[t] & (L_EXP - 1);
        const int p = atomicAdd(&off[l], 1);
        g_tok_sorted[p]  = t;
        g_slot_expert[p] = l;
    }
}

// Stage 1: xa[slot, r] += sum_{d in slice} x[tok,d] * A[l, d, r]
// 16 d-slices of 128; x staged with pitch 68 (272B rows -> conflict-free LDS.128)
__global__ void __launch_bounds__(256) xa_kernel(
    const float* __restrict__ x, const float* __restrict__ A)
{
    const int l  = blockIdx.x >> 6;
    const int ci = blockIdx.x & 63;
    const int ds = blockIdx.y;               // d-slice of 128
    const int s = g_expert_start[l];
    const int e = g_expert_start[l + 1];
    const int t0 = s + ci * 32;
    if (t0 >= e) return;
    const int count = min(32, e - t0);

    __shared__ float As[64 * 32];
    __shared__ float xs[32 * 68];
    __shared__ int   toks[32];
    const int tid = threadIdx.x;
    if (tid < 32) toks[tid] = (tid < count) ? g_tok_sorted[t0 + tid] : 0;

    const int t_local = tid & 31;
    const int rb = (tid >> 5) << 2;          // 4-aligned -> float4 A loads
    float acc0 = 0.f, acc1 = 0.f, acc2 = 0.f, acc3 = 0.f;
    const float* Abase = A + (size_t)l * D_DIM * 32;
    const int d_lo = ds * 128;

    for (int d0 = d_lo; d0 < d_lo + 128; d0 += 64) {
        __syncthreads();
        for (int i = tid; i < 64 * 32; i += 256) As[i] = Abase[(size_t)d0 * 32 + i];
        for (int i = tid; i < 32 * 64; i += 256) {
            const int tl = i >> 6, d = i & 63;
            xs[tl * 68 + d] = (tl < count) ? x[(size_t)toks[tl] * D_DIM + d0 + d] : 0.f;
        }
        __syncthreads();
        #pragma unroll 4
        for (int d4 = 0; d4 < 16; d4++) {
            const float4 xv = *reinterpret_cast<const float4*>(&xs[t_local * 68 + d4 * 4]);
            const float4 a0 = *reinterpret_cast<const float4*>(&As[(d4 * 4 + 0) * 32 + rb]);
            const float4 a1 = *reinterpret_cast<const float4*>(&As[(d4 * 4 + 1) * 32 + rb]);
            const float4 a2 = *reinterpret_cast<const float4*>(&As[(d4 * 4 + 2) * 32 + rb]);
            const float4 a3 = *reinterpret_cast<const float4*>(&As[(d4 * 4 + 3) * 32 + rb]);
            acc0 += xv.x * a0.x + xv.y * a1.x + xv.z * a2.x + xv.w * a3.x;
            acc1 += xv.x * a0.y + xv.y * a1.y + xv.z * a2.y + xv.w * a3.y;
            acc2 += xv.x * a0.z + xv.y * a1.z + xv.z * a2.z + xv.w * a3.z;
            acc3 += xv.x * a0.w + xv.y * a1.w + xv.z * a2.w + xv.w * a3.w;
        }
    }
    if (t_local < count) {
        float* o = &g_xa[(size_t)(t0 + t_local) * 32 + rb];   // slot-major
        atomicAdd(o + 0, acc0);
        atomicAdd(o + 1, acc1);
        atomicAdd(o + 2, acc2);
        atomicAdd(o + 3, acc3);
    }
}

// ======================= main GEMM + fused delta ==========================
// out[tok(m), n] = sum_k x[tok,k]*W[n,k] + sum_r xa[m, rbase+r]*B[l_m, r, n]
__global__ void __launch_bounds__(256, 2) gemm_kernel(
    const float* __restrict__ Bw, float* __restrict__ out)
{
    extern __shared__ char smem[];
    const uint32_t sbase = smem_u32(smem);
    const int tid  = threadIdx.x;
    const int lane = tid & 31;
    const int wid  = tid >> 5;
    const int wm   = wid & 3;       // warp row  (32 rows)
    const int wn   = wid >> 2;      // warp col  (64 cols)
    const int m0 = blockIdx.x * BM;
    const int n0 = blockIdx.y * BN;

    const int cp_r  = tid >> 3;
    const int cp_ch = tid & 7;

    auto issue = [&](int kc, int stage) {
        const uint32_t sb = sbase + stage * STAGE_B;
        const int kcol = kc * BK + cp_ch * 8;
        #pragma unroll
        for (int c = 0; c < 8; c++) {
            const int buf = c >> 2;
            const int r   = ((c & 3) << 5) + cp_r;
            const __half* g = (buf == 0)
                ? g_xh + (size_t)(m0 + r) * D_DIM + kcol
                : g_Wh + (size_t)(n0 + r) * D_DIM + kcol;
            cp_async16(sb + buf * TILE_B + r * PITCH_B + cp_ch * 16, g);
        }
    };

    float acc[2][8][4];
    #pragma unroll
    for (int i = 0; i < 2; i++)
        #pragma unroll
        for (int j = 0; j < 8; j++)
            #pragma unroll
            for (int q = 0; q < 4; q++) acc[i][j][q] = 0.f;

    issue(0, 0); CP_COMMIT();
    issue(1, 1); CP_COMMIT();

    const int ln16 = lane & 15;
    const uint32_t aoff = (uint32_t)((wm * 32 + ln16) * PITCH_B + (lane >> 4) * 16);
    const uint32_t boff = (uint32_t)((wn * 64 + ((lane >> 4) << 3) + (lane & 7)) * PITCH_B
                                     + ((lane >> 3) & 1) * 16);

    for (int kc = 0; kc < K_ITERS; kc++) {
        CP_WAIT(1);
        __syncthreads();
        if (kc + 2 < K_ITERS) issue(kc + 2, (kc + 2) % STAGES);
        CP_COMMIT();

        const uint32_t sb = sbase + (kc % STAGES) * STAGE_B;
        const uint32_t sA = sb;
        const uint32_t sB = sb + TILE_B;

        #pragma unroll
        for (int ks = 0; ks < 4; ks++) {
            uint32_t a0[4], a1[4];
            ldsm_x4(a0, sA + aoff + ks * 32);
            ldsm_x4(a1, sA + aoff + ks * 32 + 16 * PITCH_B);
            #pragma unroll
            for (int p = 0; p < 4; p++) {
                uint32_t b[4];
                ldsm_x4(b, sB + boff + ks * 32 + p * 16 * PITCH_B);
                mma_f16(acc[0][2 * p],     a0, b);
                mma_f16(acc[1][2 * p],     a1, b);
                mma_f16(acc[0][2 * p + 1], a0, b + 2);
                mma_f16(acc[1][2 * p + 1], a1, b + 2);
            }
        }
    }

    // =================== fused delta epilogue ===================
    CP_WAIT(0);
    __syncthreads();   // mainloop smem reads done everywhere; reuse stage memory

    float* xa_s  = reinterpret_cast<float*>(smem);            // 128*16 floats (8KB)
    float* Bs    = xa_s + 128 * 16;                           // 16*128 floats (8KB)
    int*   e_s   = reinterpret_cast<int*>(Bs + 16 * 128);     // 128 ints
    int*   tok_s = e_s + 128;                                 // 128 ints

    const int rbase = (n0 >= BDIM) ? 16 : 0;
    for (int i = tid; i < 128; i += 256) {
        e_s[i]   = g_slot_expert[m0 + i];
        tok_s[i] = g_tok_sorted[m0 + i];
    }
    for (int i = tid; i < 128 * 16; i += 256) {
        const int row = i >> 4, r = i & 15;
        xa_s[i] = g_xa[(size_t)(m0 + row) * 32 + rbase + r];
    }
    __syncthreads();

    const int e0 = e_s[0];
    const int e1 = e_s[127];   // sorted -> contiguous expert run
    for (int e = e0; e <= e1; e++) {
        const float* Bb = Bw + ((size_t)e * 16) * N_OUT + n0;
        for (int i = tid; i < 16 * 128 / 4; i += 256) {
            const int r = i >> 5, c4 = (i & 31) << 2;
            *reinterpret_cast<float4*>(&Bs[r * 128 + c4]) =
                *reinterpret_cast<const float4*>(Bb + (size_t)r * N_OUT + c4);
        }
        __syncthreads();
        #pragma unroll
        for (int mf = 0; mf < 2; mf++) {
            #pragma unroll
            for (int rr = 0; rr < 2; rr++) {
                const int row = wm * 32 + mf * 16 + rr * 8 + (lane >> 2);
                if (e_s[row] == e) {
                    float xr[16];
                    #pragma unroll
                    for (int r = 0; r < 16; r++) xr[r] = xa_s[row * 16 + r];
                    #pragma unroll
                    for (int nf = 0; nf < 8; nf++) {
                        const int c = wn * 64 + nf * 8 + (lane & 3) * 2;
                        float d0 = 0.f, d1 = 0.f;
                        #pragma unroll
                        for (int r = 0; r < 16; r++) {
                            const float2 bv = *reinterpret_cast<const float2*>(&Bs[r * 128 + c]);
                            d0 += xr[r] * bv.x;
                            d1 += xr[r] * bv.y;
                        }
                        acc[mf][nf][rr * 2 + 0] += d0;
                        acc[mf][nf][rr * 2 + 1] += d1;
                    }
                }
            }
        }
        __syncthreads();
    }

    // =================== stores (scatter rows by token) ===================
    #pragma unroll
    for (int mf = 0; mf < 2; mf++) {
        const int rowA = wm * 32 + mf * 16 + (lane >> 2);
        const int mA = tok_s[rowA];
        const int mB = tok_s[rowA + 8];
        #pragma unroll
        for (int nf = 0; nf < 8; nf++) {
            const int n = n0 + wn * 64 + nf * 8 + (lane & 3) * 2;
            float2 v0 = make_float2(acc[mf][nf][0], acc[mf][nf][1]);
            float2 v1 = make_float2(acc[mf][nf][2], acc[mf][nf][3]);
            *reinterpret_cast<float2*>(out + (size_t)mA * N_OUT + n) = v0;
            *reinterpret_cast<float2*>(out + (size_t)mB * N_OUT + n) = v1;
        }
    }
}

// ======================= launch =============================
extern "C" void kernel_launch(void* const* d_in, const int* in_sizes, int n_in,
                              void* d_out, int out_size)
{
    const float* x    = (const float*)d_in[0];
    const float* W    = (const float*)d_in[1];
    const float* A    = (const float*)d_in[2];
    const float* B    = (const float*)d_in[3];
    const int*   widx = (const int*)d_in[4];
    float* out = (float*)d_out;

    static cudaStream_t s1 = nullptr, s2 = nullptr;
    static cudaEvent_t evFork = nullptr, evSort = nullptr, evJ1 = nullptr, evJ2 = nullptr;
    if (s1 == nullptr) {
        cudaStreamCreateWithFlags(&s1, cudaStreamNonBlocking);
        cudaStreamCreateWithFlags(&s2, cudaStreamNonBlocking);
        cudaEventCreateWithFlags(&evFork, cudaEventDisableTiming);
        cudaEventCreateWithFlags(&evSort, cudaEventDisableTiming);
        cudaEventCreateWithFlags(&evJ1, cudaEventDisableTiming);
        cudaEventCreateWithFlags(&evJ2, cudaEventDisableTiming);
    }

    cudaFuncSetAttribute(gemm_kernel, cudaFuncAttributeMaxDynamicSharedMemorySize, SMEM_GEMM);

    __half *xh_p, *wh_p;
    cudaGetSymbolAddress((void**)&xh_p, g_xh);
    cudaGetSymbolAddress((void**)&wh_p, g_Wh);

    // s1: sort(+zero) -> xa
    // s2: convert_W, then (after sort) convert_x_perm
    cudaEventRecord(evFork, 0);
    cudaStreamWaitEvent(s1, evFork, 0);
    cudaStreamWaitEvent(s2, evFork, 0);

    sort_kernel<<<1, 256, 0, s1>>>(widx);
    cudaEventRecord(evSort, s1);
    xa_kernel<<<dim3(L_EXP * 64, 16), 256, 0, s1>>>(x, A);

    const int n4w = N_OUT * D_DIM / 4;
    convert_W_kernel<<<(n4w / 2 + 255) / 256, 256, 0, s2>>>((const float4*)W, (uint2*)wh_p, n4w);
    cudaStreamWaitEvent(s2, evSort, 0);
    convert_x_perm_kernel<<<T_TOK, 256, 0, s2>>>((const float4*)x, (uint2*)xh_p);

    cudaEventRecord(evJ1, s1);
    cudaEventRecord(evJ2, s2);
    cudaStreamWaitEvent(0, evJ1, 0);
    cudaStreamWaitEvent(0, evJ2, 0);

    gemm_kernel<<<dim3(MT, NT), 256, SMEM_GEMM>>>(B, out);
}